// round 11
// baseline (speedup 1.0000x reference)
#include <cuda_runtime.h>
#include <cuda_bf16.h>
#include <cstdint>

// Problem constants
#define BB 8
#define NN 128
#define LL 4096
#define DD 1024
#define HH 16
#define DH 64
#define BH (BB*HH)          // 128

// ---------------- scratch (device globals) ----------------
__device__ float g_Qp[BB*NN*DD];            // 4 MB
__device__ float g_Kp[BB*LL*DD];            // 128 MB
__device__ float g_Vp[BB*LL*DD];            // 128 MB
__device__ float g_O [BB*NN*DD];            // 4 MB

// ---------------- helpers ----------------
__device__ __forceinline__ uint32_t smem_u32(const void* p) {
    uint32_t a;
    asm("{ .reg .u64 t; cvta.to.shared.u64 t, %1; cvt.u32.u64 %0, t; }"
        : "=r"(a) : "l"(p));
    return a;
}
__device__ __forceinline__ uint32_t pk2(float x, float y) {
    uint32_t r;
    asm("cvt.rn.bf16x2.f32 %0, %1, %2;" : "=r"(r) : "f"(y), "f"(x));
    return r;
}
__device__ __forceinline__ uint32_t pk2lo(float x, float y, uint32_t h) {
    float hx = __uint_as_float(h << 16);
    float hy = __uint_as_float(h & 0xFFFF0000u);
    uint32_t r;
    asm("cvt.rn.bf16x2.f32 %0, %1, %2;" : "=r"(r) : "f"(y - hy), "f"(x - hx));
    return r;
}
__device__ __forceinline__ void pack_hl(float4 v, uint64_t& H, uint64_t& L) {
    uint32_t h01 = pk2(v.x, v.y);
    uint32_t h23 = pk2(v.z, v.w);
    uint32_t l01 = pk2lo(v.x, v.y, h01);
    uint32_t l23 = pk2lo(v.z, v.w, h23);
    H = (uint64_t)h01 | ((uint64_t)h23 << 32);
    L = (uint64_t)l01 | ((uint64_t)l23 << 32);
}
__device__ __forceinline__ uint64_t pack_h(float4 v) {
    uint32_t h01 = pk2(v.x, v.y);
    uint32_t h23 = pk2(v.z, v.w);
    return (uint64_t)h01 | ((uint64_t)h23 << 32);
}
__device__ __forceinline__ void sts64(uint32_t addr, uint64_t v) {
    asm volatile("st.shared.b64 [%0], %1;" :: "r"(addr), "l"(v) : "memory");
}
__device__ __forceinline__ void sts32(uint32_t addr, uint32_t v) {
    asm volatile("st.shared.b32 [%0], %1;" :: "r"(addr), "r"(v) : "memory");
}
__device__ __forceinline__ void cp16(uint32_t s, const void* g) {
    asm volatile("cp.async.cg.shared.global [%0], [%1], 16;" :: "r"(s), "l"(g));
}
#define CP_COMMIT() asm volatile("cp.async.commit_group;" ::: "memory")
#define CP_WAIT0()  asm volatile("cp.async.wait_group 0;" ::: "memory")

#define LDSM4(r, a) \
    asm volatile("ldmatrix.sync.aligned.m8n8.x4.shared.b16 {%0,%1,%2,%3}, [%4];" \
        : "=r"((r)[0]), "=r"((r)[1]), "=r"((r)[2]), "=r"((r)[3]) : "r"(a))
#define LDSM4T(r, a) \
    asm volatile("ldmatrix.sync.aligned.m8n8.x4.trans.shared.b16 {%0,%1,%2,%3}, [%4];" \
        : "=r"((r)[0]), "=r"((r)[1]), "=r"((r)[2]), "=r"((r)[3]) : "r"(a))

#define MMA16816(d, a, b) \
    asm volatile("mma.sync.aligned.m16n8k16.row.col.f32.bf16.bf16.f32 " \
        "{%0,%1,%2,%3}, {%4,%5,%6,%7}, {%8,%9}, {%0,%1,%2,%3};" \
        : "+f"((d)[0]), "+f"((d)[1]), "+f"((d)[2]), "+f"((d)[3]) \
        : "r"((a)[0]), "r"((a)[1]), "r"((a)[2]), "r"((a)[3]), \
          "r"((b)[0]), "r"((b)[1]))

// ---------------- bf16 NT GEMM: C = alpha * A @ B^T --------------------------
// Tile 128x64, BK = 32 fp32, 8 warps = 4(m) x 2(n), warp tile 32x32, occ 2.
// SMEM rows: 144B pitch, [hi 64B | lo 64B | pad].
// NPASS=3: bf16x3 split (hi*hi + hi*lo + lo*hi), rel err ~2e-6.
// NPASS=1: plain bf16 (hi*hi only), rel err ~1.6e-3 — K projection only
//          (its error enters the output only through the softmax weights).
template<int NPASS>
__global__ void __launch_bounds__(256, 2)
gemm_mma(const float* __restrict__ A, const float* __restrict__ Bp,
         float* __restrict__ Cg, int K, int lda, int ldb, int ldc, float alpha)
{
    constexpr int ABYTES = 128 * 144;
    constexpr int BBYTES = 64 * 144;
    constexpr int STAGE  = ABYTES + BBYTES;

    extern __shared__ char smem[];
    const uint32_t sb = smem_u32(smem);

    const int tid  = threadIdx.x;
    const int wid  = tid >> 5, lane = tid & 31;
    const int wm   = wid & 3, wn = wid >> 2;          // 4 x 2

    const int m0 = blockIdx.y * 128;
    const int n0 = blockIdx.x * 64;

    float acc[2][4][4];
#pragma unroll
    for (int i = 0; i < 2; i++)
#pragma unroll
        for (int j = 0; j < 4; j++)
#pragma unroll
            for (int q = 0; q < 4; q++) acc[i][j][q] = 0.f;

    const int NC = K >> 5;
    float4 ra[4], rb[2];
    const int lrow = tid >> 3;
    const int lseg = tid & 7;

    auto ldg = [&](int c) {
        const int k0 = c << 5;
#pragma unroll
        for (int i = 0; i < 4; i++)
            ra[i] = *reinterpret_cast<const float4*>(
                &A[(long)(m0 + lrow + (i << 5)) * lda + k0 + (lseg << 2)]);
#pragma unroll
        for (int i = 0; i < 2; i++)
            rb[i] = *reinterpret_cast<const float4*>(
                &Bp[(long)(n0 + lrow + (i << 5)) * ldb + k0 + (lseg << 2)]);
    };
    auto sts_stage = [&](int st) {
        const uint32_t abase = sb + st * STAGE;
        const uint32_t bbase = abase + ABYTES;
#pragma unroll
        for (int i = 0; i < 4; i++) {
            uint32_t o = (uint32_t)((lrow + (i << 5)) * 144 + (lseg << 3));
            if (NPASS == 3) {
                uint64_t H, L; pack_hl(ra[i], H, L);
                sts64(abase + o, H); sts64(abase + o + 64, L);
            } else {
                sts64(abase + o, pack_h(ra[i]));
            }
        }
#pragma unroll
        for (int i = 0; i < 2; i++) {
            uint32_t o = (uint32_t)((lrow + (i << 5)) * 144 + (lseg << 3));
            if (NPASS == 3) {
                uint64_t H, L; pack_hl(rb[i], H, L);
                sts64(bbase + o, H); sts64(bbase + o + 64, L);
            } else {
                sts64(bbase + o, pack_h(rb[i]));
            }
        }
    };
    auto compute = [&](int st) {
        const uint32_t abase = sb + st * STAGE;
        const uint32_t bbase = abase + ABYTES;
        const uint32_t lmo = (uint32_t)(((lane & 15) * 144) + ((lane >> 4) << 4));
#pragma unroll
        for (int ks = 0; ks < 2; ks++) {
            uint32_t ah[2][4], al[2][4];
#pragma unroll
            for (int mt = 0; mt < 2; mt++) {
                uint32_t ad = abase + (uint32_t)((wm * 32 + mt * 16) * 144 + ks * 32) + lmo;
                LDSM4(ah[mt], ad);
                if (NPASS == 3) LDSM4(al[mt], ad + 64);
            }
            uint32_t bhp[4][2], blp[4][2];
#pragma unroll
            for (int j = 0; j < 2; j++) {
                uint32_t bd = bbase + (uint32_t)((wn * 32 + j * 16) * 144 + ks * 32) + lmo;
                uint32_t t[4];
                LDSM4(t, bd);
                bhp[2*j][0] = t[0]; bhp[2*j][1] = t[2];
                bhp[2*j+1][0] = t[1]; bhp[2*j+1][1] = t[3];
                if (NPASS == 3) {
                    LDSM4(t, bd + 64);
                    blp[2*j][0] = t[0]; blp[2*j][1] = t[2];
                    blp[2*j+1][0] = t[1]; blp[2*j+1][1] = t[3];
                }
            }
            // independent sweeps: each accumulator revisited every 8 MMAs
#pragma unroll
            for (int mt = 0; mt < 2; mt++)
#pragma unroll
                for (int nt = 0; nt < 4; nt++)
                    MMA16816(acc[mt][nt], ah[mt], bhp[nt]);
            if (NPASS == 3) {
#pragma unroll
                for (int mt = 0; mt < 2; mt++)
#pragma unroll
                    for (int nt = 0; nt < 4; nt++)
                        MMA16816(acc[mt][nt], ah[mt], blp[nt]);
#pragma unroll
                for (int mt = 0; mt < 2; mt++)
#pragma unroll
                    for (int nt = 0; nt < 4; nt++)
                        MMA16816(acc[mt][nt], al[mt], bhp[nt]);
            }
        }
    };

    ldg(0);
    sts_stage(0);
    __syncthreads();

    for (int c = 0; c < NC; c++) {
        if (c + 1 < NC) ldg(c + 1);
        compute(c & 1);
        if (c + 1 < NC) sts_stage((c + 1) & 1);
        __syncthreads();
    }

#pragma unroll
    for (int mt = 0; mt < 2; mt++) {
        int mr = m0 + wm * 32 + mt * 16 + (lane >> 2);
#pragma unroll
        for (int nt = 0; nt < 4; nt++) {
            int col = n0 + wn * 32 + nt * 8 + (lane & 3) * 2;
            float2 v0, v1;
            v0.x = acc[mt][nt][0] * alpha; v0.y = acc[mt][nt][1] * alpha;
            v1.x = acc[mt][nt][2] * alpha; v1.y = acc[mt][nt][3] * alpha;
            *reinterpret_cast<float2*>(&Cg[(long)mr * ldc + col]) = v0;
            *reinterpret_cast<float2*>(&Cg[(long)(mr + 8) * ldc + col]) = v1;
        }
    }
}

// ---------------- fused attention (R9 proven: 3-pass MMA1 + 3-pass MMA2) -----
// One CTA per (b,h). S = Q@K^T chunkwise in bf16x3; exact column softmax over
// n=128 (no max subtraction); P@[V|ones] in bf16x3; divide by rowsum.
#define FPK 144
#define FPV 176
#define QHI_O 0
#define QLO_O 18432
#define KHI_O 36864
#define KLO_O 55296
#define VHI_O 73728
#define VLO_O 96256
#define STK_O 118784
#define STV_O 151552
#define CST_O 184320
#define FUSED_SMEM (CST_O + 9*128*4)   // 188928

__global__ void __launch_bounds__(256, 1)
fused_attn(const float* __restrict__ Qp, const float* __restrict__ Kp,
           const float* __restrict__ Vp, float* __restrict__ O)
{
    extern __shared__ char smem[];
    const uint32_t sb = smem_u32(smem);
    float* cst = reinterpret_cast<float*>(smem + CST_O);

    const int tid = threadIdx.x, wid = tid >> 5, lane = tid & 31;
    const int bh = blockIdx.x, b = bh >> 4, h = bh & 15;
    const float* Qg = Qp + (long)b * NN * DD + h * DH;
    const float* Kg = Kp + (long)b * LL * DD + h * DH;
    const float* Vg = Vp + (long)b * LL * DD + h * DH;

    const uint32_t QHI = sb + QHI_O, QLO = sb + QLO_O;
    const uint32_t KHI = sb + KHI_O, KLO = sb + KLO_O;
    const uint32_t VHI = sb + VHI_O, VLO = sb + VLO_O;
    const uint32_t STK = sb + STK_O, STV = sb + STV_O;

    for (int r = tid; r < 128; r += 256) {
        uint32_t ro = (uint32_t)r * FPV;
#pragma unroll
        for (int cb = 0; cb < 4; cb++) {
            sts32(VHI + ro + 128 + cb * 4, 0x3F803F80u);
            sts32(VLO + ro + 128 + cb * 4, 0u);
            sts32(VHI + ro + 144 + cb * 4, 0u);
            sts32(VLO + ro + 144 + cb * 4, 0u);
        }
    }

    const float SCALE = 0.03125f;
#pragma unroll
    for (int i = 0; i < 8; i++) {
        int idx = tid + i * 256;
        int r = idx >> 4, s = idx & 15;
        float4 v = *reinterpret_cast<const float4*>(&Qg[(long)r * DD + s * 4]);
        v.x *= SCALE; v.y *= SCALE; v.z *= SCALE; v.w *= SCALE;
        uint64_t H, L; pack_hl(v, H, L);
        sts64(QHI + r * FPK + s * 8, H);
        sts64(QLO + r * FPK + s * 8, L);
    }

    auto cpasync_chunk = [&](int c) {
        long l0 = (long)c * 128;
#pragma unroll
        for (int i = 0; i < 8; i++) {
            int idx = tid + i * 256;
            int r = idx >> 4, s = idx & 15;
            cp16(STK + (uint32_t)(r * 256 + s * 16), &Kg[(l0 + r) * DD + s * 4]);
            cp16(STV + (uint32_t)(r * 256 + s * 16), &Vg[(l0 + r) * DD + s * 4]);
        }
        CP_COMMIT();
    };
    auto cvt_chunk = [&]() {
        const float4* stk = reinterpret_cast<const float4*>(smem + STK_O);
        const float4* stv = reinterpret_cast<const float4*>(smem + STV_O);
#pragma unroll
        for (int i = 0; i < 8; i++) {
            int idx = tid + i * 256;
            int r = idx >> 4, s = idx & 15;
            uint64_t H, L;
            pack_hl(stk[r * 16 + s], H, L);
            sts64(KHI + r * FPK + s * 8, H);
            sts64(KLO + r * FPK + s * 8, L);
            pack_hl(stv[r * 16 + s], H, L);
            sts64(VHI + r * FPV + s * 8, H);
            sts64(VLO + r * FPV + s * 8, L);
        }
    };

    float acc2[9][4];
#pragma unroll
    for (int i = 0; i < 9; i++)
#pragma unroll
        for (int j = 0; j < 4; j++) acc2[i][j] = 0.f;

    const int mrow = wid * 16;
    const uint32_t lqk = (uint32_t)((lane & 15) * FPK + ((lane >> 4) << 4));
    const uint32_t lv  = (uint32_t)((lane & 15) * FPV + ((lane >> 4) << 4));

    cpasync_chunk(0);
    CP_WAIT0();
    __syncthreads();
    cvt_chunk();
    __syncthreads();

    for (int c = 0; c < 32; c++) {
        if (c + 1 < 32) cpasync_chunk(c + 1);

        float acc1[16][4];
#pragma unroll
        for (int i = 0; i < 16; i++)
#pragma unroll
            for (int j = 0; j < 4; j++) acc1[i][j] = 0.f;

#pragma unroll
        for (int ks = 0; ks < 4; ks++) {
            uint32_t ah[4], al[4];
            LDSM4(ah, QHI + (uint32_t)(mrow * FPK + ks * 32) + lqk);
            LDSM4(al, QLO + (uint32_t)(mrow * FPK + ks * 32) + lqk);
#pragma unroll
            for (int nt2 = 0; nt2 < 8; nt2++) {
                uint32_t th[4], tl[4];
                LDSM4(th, KHI + (uint32_t)(nt2 * 16 * FPK + ks * 32) + lqk);
                LDSM4(tl, KLO + (uint32_t)(nt2 * 16 * FPK + ks * 32) + lqk);
                uint32_t b0h[2] = {th[0], th[2]}, b1h[2] = {th[1], th[3]};
                uint32_t b0l[2] = {tl[0], tl[2]}, b1l[2] = {tl[1], tl[3]};
                MMA16816(acc1[2*nt2],   ah, b0h);
                MMA16816(acc1[2*nt2],   ah, b0l);
                MMA16816(acc1[2*nt2],   al, b0h);
                MMA16816(acc1[2*nt2+1], ah, b1h);
                MMA16816(acc1[2*nt2+1], ah, b1l);
                MMA16816(acc1[2*nt2+1], al, b1h);
            }
        }

#pragma unroll
        for (int nt = 0; nt < 16; nt++) {
            acc1[nt][0] = __expf(acc1[nt][0]);
            acc1[nt][1] = __expf(acc1[nt][1]);
            acc1[nt][2] = __expf(acc1[nt][2]);
            acc1[nt][3] = __expf(acc1[nt][3]);
            float s0 = acc1[nt][0] + acc1[nt][2];
            float s1 = acc1[nt][1] + acc1[nt][3];
            s0 += __shfl_xor_sync(0xffffffffu, s0, 4);
            s0 += __shfl_xor_sync(0xffffffffu, s0, 8);
            s0 += __shfl_xor_sync(0xffffffffu, s0, 16);
            s1 += __shfl_xor_sync(0xffffffffu, s1, 4);
            s1 += __shfl_xor_sync(0xffffffffu, s1, 8);
            s1 += __shfl_xor_sync(0xffffffffu, s1, 16);
            if (lane < 4) {
                cst[wid * 128 + nt * 8 + lane * 2]     = s0;
                cst[wid * 128 + nt * 8 + lane * 2 + 1] = s1;
            }
        }
        __syncthreads();
        if (tid < 128) {
            float s = 0.f;
#pragma unroll
            for (int w = 0; w < 8; w++) s += cst[w * 128 + tid];
            cst[1024 + tid] = 1.f / s;
        }
        __syncthreads();
#pragma unroll
        for (int nt = 0; nt < 16; nt++) {
            float2 iv = *reinterpret_cast<const float2*>(
                &cst[1024 + nt * 8 + (lane & 3) * 2]);
            acc1[nt][0] *= iv.x; acc1[nt][1] *= iv.y;
            acc1[nt][2] *= iv.x; acc1[nt][3] *= iv.y;
        }

#pragma unroll
        for (int ks2 = 0; ks2 < 8; ks2++) {
            const float* p0 = acc1[2*ks2];
            const float* p1 = acc1[2*ks2+1];
            uint32_t pah[4], pal[4];
            pah[0] = pk2(p0[0], p0[1]); pal[0] = pk2lo(p0[0], p0[1], pah[0]);
            pah[1] = pk2(p0[2], p0[3]); pal[1] = pk2lo(p0[2], p0[3], pah[1]);
            pah[2] = pk2(p1[0], p1[1]); pal[2] = pk2lo(p1[0], p1[1], pah[2]);
            pah[3] = pk2(p1[2], p1[3]); pal[3] = pk2lo(p1[2], p1[3], pah[3]);
#pragma unroll
            for (int nt2 = 0; nt2 < 5; nt2++) {
                uint32_t th[4], tl[4];
                LDSM4T(th, VHI + (uint32_t)(ks2 * 16 * FPV + nt2 * 32) + lv);
                LDSM4T(tl, VLO + (uint32_t)(ks2 * 16 * FPV + nt2 * 32) + lv);
                uint32_t b0h[2] = {th[0], th[1]}, b0l[2] = {tl[0], tl[1]};
                MMA16816(acc2[2*nt2], pah, b0h);
                MMA16816(acc2[2*nt2], pah, b0l);
                MMA16816(acc2[2*nt2], pal, b0h);
                if (nt2 < 4) {
                    uint32_t b1h[2] = {th[2], th[3]}, b1l[2] = {tl[2], tl[3]};
                    MMA16816(acc2[2*nt2+1], pah, b1h);
                    MMA16816(acc2[2*nt2+1], pah, b1l);
                    MMA16816(acc2[2*nt2+1], pal, b1h);
                }
            }
        }

        if (c + 1 < 32) CP_WAIT0();
        __syncthreads();
        if (c + 1 < 32) {
            cvt_chunk();
            __syncthreads();
        }
    }

    float rs0 = __shfl_sync(0xffffffffu, acc2[8][0], lane & ~3);
    float rs2 = __shfl_sync(0xffffffffu, acc2[8][2], lane & ~3);
    float i0 = 1.f / rs0, i2 = 1.f / rs2;
    int r0 = mrow + (lane >> 2);
    float* Ob = O + (long)b * NN * DD + h * DH;
#pragma unroll
    for (int nt = 0; nt < 8; nt++) {
        int cc = nt * 8 + (lane & 3) * 2;
        float2 v0, v1;
        v0.x = acc2[nt][0] * i0; v0.y = acc2[nt][1] * i0;
        v1.x = acc2[nt][2] * i2; v1.y = acc2[nt][3] * i2;
        *reinterpret_cast<float2*>(&Ob[(long)r0 * DD + cc]) = v0;
        *reinterpret_cast<float2*>(&Ob[(long)(r0 + 8) * DD + cc]) = v1;
    }
}

// ---------------- launch ----------------------------------------------------
extern "C" void kernel_launch(void* const* d_in, const int* in_sizes, int n_in,
                              void* d_out, int out_size)
{
    const float* q  = (const float*)d_in[0];
    const float* k  = (const float*)d_in[1];
    const float* v  = (const float*)d_in[2];
    const float* Wq = (const float*)d_in[3];
    const float* Wk = (const float*)d_in[4];
    const float* Wv = (const float*)d_in[5];
    const float* Wo = (const float*)d_in[6];
    float* out = (float*)d_out;

    float *Qp, *Kp, *Vp, *O;
    cudaGetSymbolAddress((void**)&Qp, g_Qp);
    cudaGetSymbolAddress((void**)&Kp, g_Kp);
    cudaGetSymbolAddress((void**)&Vp, g_Vp);
    cudaGetSymbolAddress((void**)&O,  g_O);

    const int SZG = 2 * (128 * 144 + 64 * 144);   // 55296
    cudaFuncSetAttribute((const void*)gemm_mma<3>,
                         cudaFuncAttributeMaxDynamicSharedMemorySize, SZG);
    cudaFuncSetAttribute((const void*)gemm_mma<1>,
                         cudaFuncAttributeMaxDynamicSharedMemorySize, SZG);
    cudaFuncSetAttribute((const void*)fused_attn,
                         cudaFuncAttributeMaxDynamicSharedMemorySize, FUSED_SMEM);

    // Q projection: full precision (cheap)
    gemm_mma<3><<<dim3(DD/64, (BB*NN)/128), 256, SZG>>>(
        q, Wq, Qp, DD, DD, DD, DD, 1.f);
    // K projection: plain bf16 (error enters only via softmax weights)
    gemm_mma<1><<<dim3(DD/64, (BB*LL)/128), 256, SZG>>>(
        k, Wk, Kp, DD, DD, DD, DD, 1.f);
    // V projection: full bf16x3 (errors hit the output directly)
    gemm_mma<3><<<dim3(DD/64, (BB*LL)/128), 256, SZG>>>(
        v, Wv, Vp, DD, DD, DD, DD, 1.f);

    // fused: scores (bf16x3) + inverted softmax + L1 renorm + AV (bf16x3)
    fused_attn<<<BH, 256, FUSED_SMEM>>>(Qp, Kp, Vp, O);

    // output projection: full bf16x3
    gemm_mma<3><<<dim3(DD/64, (BB*NN)/128), 256, SZG>>>(
        O, Wo, out, DD, DD, DD, DD, 1.f);
}

// round 13
// speedup vs baseline: 1.0169x; 1.0169x over previous
#include <cuda_runtime.h>
#include <cuda_bf16.h>
#include <cstdint>

// Problem constants
#define BB 8
#define NN 128
#define LL 4096
#define DD 1024
#define HH 16
#define DH 64
#define BH (BB*HH)          // 128

// ---------------- scratch (device globals) ----------------
__device__ float g_Qp[BB*NN*DD];            // 4 MB
__device__ float g_Kp[BB*LL*DD];            // 128 MB
__device__ float g_Vp[BB*LL*DD];            // 128 MB
__device__ float g_O [BB*NN*DD];            // 4 MB

// ---------------- helpers ----------------
__device__ __forceinline__ uint32_t smem_u32(const void* p) {
    uint32_t a;
    asm("{ .reg .u64 t; cvta.to.shared.u64 t, %1; cvt.u32.u64 %0, t; }"
        : "=r"(a) : "l"(p));
    return a;
}
__device__ __forceinline__ uint32_t pk2(float x, float y) {
    uint32_t r;
    asm("cvt.rn.bf16x2.f32 %0, %1, %2;" : "=r"(r) : "f"(y), "f"(x));
    return r;
}
__device__ __forceinline__ uint32_t pk2lo(float x, float y, uint32_t h) {
    float hx = __uint_as_float(h << 16);
    float hy = __uint_as_float(h & 0xFFFF0000u);
    uint32_t r;
    asm("cvt.rn.bf16x2.f32 %0, %1, %2;" : "=r"(r) : "f"(y - hy), "f"(x - hx));
    return r;
}
__device__ __forceinline__ void pack_hl(float4 v, uint64_t& H, uint64_t& L) {
    uint32_t h01 = pk2(v.x, v.y);
    uint32_t h23 = pk2(v.z, v.w);
    uint32_t l01 = pk2lo(v.x, v.y, h01);
    uint32_t l23 = pk2lo(v.z, v.w, h23);
    H = (uint64_t)h01 | ((uint64_t)h23 << 32);
    L = (uint64_t)l01 | ((uint64_t)l23 << 32);
}
__device__ __forceinline__ uint32_t f2tf(float x) {
    uint32_t r;
    asm("cvt.rna.tf32.f32 %0, %1;" : "=r"(r) : "f"(x));
    return r;
}
__device__ __forceinline__ void sts64(uint32_t addr, uint64_t v) {
    asm volatile("st.shared.b64 [%0], %1;" :: "r"(addr), "l"(v) : "memory");
}
__device__ __forceinline__ void sts32(uint32_t addr, uint32_t v) {
    asm volatile("st.shared.b32 [%0], %1;" :: "r"(addr), "r"(v) : "memory");
}
__device__ __forceinline__ void sts_tf4(uint32_t addr, float4 v) {
    asm volatile("st.shared.v4.b32 [%0], {%1,%2,%3,%4};"
        :: "r"(addr), "r"(f2tf(v.x)), "r"(f2tf(v.y)),
           "r"(f2tf(v.z)), "r"(f2tf(v.w)) : "memory");
}
__device__ __forceinline__ float4 lds128f(uint32_t addr) {
    float4 v;
    asm volatile("ld.shared.v4.f32 {%0,%1,%2,%3}, [%4];"
        : "=f"(v.x), "=f"(v.y), "=f"(v.z), "=f"(v.w) : "r"(addr));
    return v;
}
__device__ __forceinline__ void cp16(uint32_t s, const void* g) {
    asm volatile("cp.async.cg.shared.global [%0], [%1], 16;" :: "r"(s), "l"(g));
}
#define CP_COMMIT() asm volatile("cp.async.commit_group;" ::: "memory")
#define CP_WAIT0()  asm volatile("cp.async.wait_group 0;" ::: "memory")

#define LDSM4(r, a) \
    asm volatile("ldmatrix.sync.aligned.m8n8.x4.shared.b16 {%0,%1,%2,%3}, [%4];" \
        : "=r"((r)[0]), "=r"((r)[1]), "=r"((r)[2]), "=r"((r)[3]) : "r"(a))
#define LDSM4T(r, a) \
    asm volatile("ldmatrix.sync.aligned.m8n8.x4.trans.shared.b16 {%0,%1,%2,%3}, [%4];" \
        : "=r"((r)[0]), "=r"((r)[1]), "=r"((r)[2]), "=r"((r)[3]) : "r"(a))

#define MMA16816(d, a, b) \
    asm volatile("mma.sync.aligned.m16n8k16.row.col.f32.bf16.bf16.f32 " \
        "{%0,%1,%2,%3}, {%4,%5,%6,%7}, {%8,%9}, {%0,%1,%2,%3};" \
        : "+f"((d)[0]), "+f"((d)[1]), "+f"((d)[2]), "+f"((d)[3]) \
        : "r"((a)[0]), "r"((a)[1]), "r"((a)[2]), "r"((a)[3]), \
          "r"((b)[0]), "r"((b)[1]))

#define MMATF32(d, a, b) \
    asm volatile("mma.sync.aligned.m16n8k8.row.col.f32.tf32.tf32.f32 " \
        "{%0,%1,%2,%3}, {%4,%5,%6,%7}, {%8,%9}, {%0,%1,%2,%3};" \
        : "+f"((d)[0]), "+f"((d)[1]), "+f"((d)[2]), "+f"((d)[3]) \
        : "r"((a)[0]), "r"((a)[1]), "r"((a)[2]), "r"((a)[3]), \
          "r"((b)[0]), "r"((b)[1]))

// ---------------- tf32 NT GEMM: C = alpha * A @ B^T --------------------------
// Tile 128x64, BK = 32 fp32 (= 4 k8 MMA steps), 8 warps = 4(m) x 2(n),
// warp tile 32x32, occ 2. SMEM rows: 144B pitch (128B tf32 data + pad).
// 1-pass tf32 via cvt.rna: GEMM rel err ~2e-4.
__global__ void __launch_bounds__(256, 2)
gemm_tf32(const float* __restrict__ A, const float* __restrict__ Bp,
          float* __restrict__ Cg, int K, int lda, int ldb, int ldc, float alpha)
{
    constexpr int ABYTES = 128 * 144;
    constexpr int BBYTES = 64 * 144;
    constexpr int STAGE  = ABYTES + BBYTES;

    extern __shared__ char smem[];
    const uint32_t sb = smem_u32(smem);

    const int tid  = threadIdx.x;
    const int wid  = tid >> 5, lane = tid & 31;
    const int wm   = wid & 3, wn = wid >> 2;          // 4 x 2

    const int m0 = blockIdx.y * 128;
    const int n0 = blockIdx.x * 64;

    float acc[2][4][4];
#pragma unroll
    for (int i = 0; i < 2; i++)
#pragma unroll
        for (int j = 0; j < 4; j++)
#pragma unroll
            for (int q = 0; q < 4; q++) acc[i][j][q] = 0.f;

    const int NC = K >> 5;
    float4 ra[4], rb[2];
    const int lrow = tid >> 3;
    const int lseg = tid & 7;

    auto ldg = [&](int c) {
        const int k0 = c << 5;
#pragma unroll
        for (int i = 0; i < 4; i++)
            ra[i] = *reinterpret_cast<const float4*>(
                &A[(long)(m0 + lrow + (i << 5)) * lda + k0 + (lseg << 2)]);
#pragma unroll
        for (int i = 0; i < 2; i++)
            rb[i] = *reinterpret_cast<const float4*>(
                &Bp[(long)(n0 + lrow + (i << 5)) * ldb + k0 + (lseg << 2)]);
    };
    auto sts_stage = [&](int st) {
        const uint32_t abase = sb + st * STAGE;
        const uint32_t bbase = abase + ABYTES;
#pragma unroll
        for (int i = 0; i < 4; i++)
            sts_tf4(abase + (uint32_t)((lrow + (i << 5)) * 144 + (lseg << 4)), ra[i]);
#pragma unroll
        for (int i = 0; i < 2; i++)
            sts_tf4(bbase + (uint32_t)((lrow + (i << 5)) * 144 + (lseg << 4)), rb[i]);
    };
    auto compute = [&](int st) {
        const uint32_t abase = sb + st * STAGE;
        const uint32_t bbase = abase + ABYTES;
        const uint32_t lmo = (uint32_t)(((lane & 15) * 144) + ((lane >> 4) << 4));
#pragma unroll
        for (int ks = 0; ks < 4; ks++) {
            uint32_t ah[2][4];
#pragma unroll
            for (int mt = 0; mt < 2; mt++)
                LDSM4(ah[mt], abase + (uint32_t)((wm * 32 + mt * 16) * 144 + ks * 32) + lmo);
            uint32_t bp[4][2];
#pragma unroll
            for (int j = 0; j < 2; j++) {
                uint32_t t[4];
                LDSM4(t, bbase + (uint32_t)((wn * 32 + j * 16) * 144 + ks * 32) + lmo);
                bp[2*j][0] = t[0]; bp[2*j][1] = t[2];
                bp[2*j+1][0] = t[1]; bp[2*j+1][1] = t[3];
            }
#pragma unroll
            for (int mt = 0; mt < 2; mt++)
#pragma unroll
                for (int nt = 0; nt < 4; nt++)
                    MMATF32(acc[mt][nt], ah[mt], bp[nt]);
        }
    };

    ldg(0);
    sts_stage(0);
    __syncthreads();

    for (int c = 0; c < NC; c++) {
        if (c + 1 < NC) ldg(c + 1);
        compute(c & 1);
        if (c + 1 < NC) sts_stage((c + 1) & 1);
        __syncthreads();
    }

#pragma unroll
    for (int mt = 0; mt < 2; mt++) {
        int mr = m0 + wm * 32 + mt * 16 + (lane >> 2);
#pragma unroll
        for (int nt = 0; nt < 4; nt++) {
            int col = n0 + wn * 32 + nt * 8 + (lane & 3) * 2;
            float2 v0, v1;
            v0.x = acc[mt][nt][0] * alpha; v0.y = acc[mt][nt][1] * alpha;
            v1.x = acc[mt][nt][2] * alpha; v1.y = acc[mt][nt][3] * alpha;
            *reinterpret_cast<float2*>(&Cg[(long)mr * ldc + col]) = v0;
            *reinterpret_cast<float2*>(&Cg[(long)(mr + 8) * ldc + col]) = v1;
        }
    }
}

// ---------------- fused attention --------------------------------------------
// One CTA per (b,h). S = Q@K^T in 1-pass tf32 (K cp.async'd raw into
// double-buffered tiles, RNE-converted in place); exact column softmax over
// n=128 (no max subtraction); P@[V|ones] in bf16x3; divide by rowsum.
#define FQP 272            // Q/K tf32 pitch (256B data + 16 pad)
#define FPV 176            // V bf16 plane pitch
#define QT_O 0             // 128*272 = 34816
#define KT_O 34816         // 2 stages x 34816 = 69632
#define VHI_O 104448       // 22528
#define VLO_O 126976       // 22528
#define STV_O 149504       // 32768 (V fp32 staging)
#define CST_O 182272       // 4608
#define FUSED_SMEM 186880

__global__ void __launch_bounds__(256, 1)
fused_attn(const float* __restrict__ Qp, const float* __restrict__ Kp,
           const float* __restrict__ Vp, float* __restrict__ O)
{
    extern __shared__ char smem[];
    const uint32_t sb = smem_u32(smem);
    float* cst = reinterpret_cast<float*>(smem + CST_O);

    const int tid = threadIdx.x, wid = tid >> 5, lane = tid & 31;
    const int bh = blockIdx.x, b = bh >> 4, h = bh & 15;
    const float* Qg = Qp + (long)b * NN * DD + h * DH;
    const float* Kg = Kp + (long)b * LL * DD + h * DH;
    const float* Vg = Vp + (long)b * LL * DD + h * DH;

    const uint32_t QT  = sb + QT_O;
    const uint32_t VHI = sb + VHI_O, VLO = sb + VLO_O;
    const uint32_t STV = sb + STV_O;

    // init V ones columns (64..71) + zero pad (72..79), both planes
    for (int r = tid; r < 128; r += 256) {
        uint32_t ro = (uint32_t)r * FPV;
#pragma unroll
        for (int cb = 0; cb < 4; cb++) {
            sts32(VHI + ro + 128 + cb * 4, 0x3F803F80u);
            sts32(VLO + ro + 128 + cb * 4, 0u);
            sts32(VHI + ro + 144 + cb * 4, 0u);
            sts32(VLO + ro + 144 + cb * 4, 0u);
        }
    }

    // load Q (scaled by D^-0.5) into tf32 tile
    const float SCALE = 0.03125f;
#pragma unroll
    for (int i = 0; i < 8; i++) {
        int idx = tid + i * 256;
        int r = idx >> 4, s = idx & 15;
        float4 v = *reinterpret_cast<const float4*>(&Qg[(long)r * DD + s * 4]);
        v.x *= SCALE; v.y *= SCALE; v.z *= SCALE; v.w *= SCALE;
        sts_tf4(QT + (uint32_t)(r * FQP + s * 16), v);
    }

    auto prefetch = [&](int c, int st) {
        long l0 = (long)c * 128;
        const uint32_t kt = sb + KT_O + (uint32_t)st * 34816u;
#pragma unroll
        for (int i = 0; i < 8; i++) {
            int idx = tid + i * 256;
            int r = idx >> 4, s = idx & 15;
            cp16(kt + (uint32_t)(r * FQP + s * 16), &Kg[(l0 + r) * DD + s * 4]);
            cp16(STV + (uint32_t)(r * 256 + s * 16), &Vg[(l0 + r) * DD + s * 4]);
        }
        CP_COMMIT();
    };
    auto cvt_chunk = [&](int st) {
        const uint32_t kt = sb + KT_O + (uint32_t)st * 34816u;
        const float4* stv = reinterpret_cast<const float4*>(smem + STV_O);
#pragma unroll
        for (int i = 0; i < 8; i++) {
            int idx = tid + i * 256;
            int r = idx >> 4, s = idx & 15;
            uint32_t a = kt + (uint32_t)(r * FQP + s * 16);
            sts_tf4(a, lds128f(a));                    // K: fp32 -> tf32 in place
            uint64_t H, L;
            pack_hl(stv[r * 16 + s], H, L);            // V: staging -> bf16 planes
            sts64(VHI + r * FPV + s * 8, H);
            sts64(VLO + r * FPV + s * 8, L);
        }
    };

    float acc2[9][4];
#pragma unroll
    for (int i = 0; i < 9; i++)
#pragma unroll
        for (int j = 0; j < 4; j++) acc2[i][j] = 0.f;

    const int mrow = wid * 16;
    const uint32_t lq = (uint32_t)((lane & 15) * FQP + ((lane >> 4) << 4));
    const uint32_t lv = (uint32_t)((lane & 15) * FPV + ((lane >> 4) << 4));

    prefetch(0, 0);
    CP_WAIT0();
    __syncthreads();
    cvt_chunk(0);
    __syncthreads();

    for (int c = 0; c < 32; c++) {
        if (c + 1 < 32) prefetch(c + 1, (c + 1) & 1);

        const uint32_t KT = sb + KT_O + (uint32_t)(c & 1) * 34816u;

        // ---- MMA1: S fragments in 1-pass tf32 (K=64 -> 8 k8 steps)
        float acc1[16][4];
#pragma unroll
        for (int i = 0; i < 16; i++)
#pragma unroll
            for (int j = 0; j < 4; j++) acc1[i][j] = 0.f;

#pragma unroll
        for (int ks = 0; ks < 8; ks++) {
            uint32_t ah[4];
            LDSM4(ah, QT + (uint32_t)(mrow * FQP + ks * 32) + lq);
#pragma unroll
            for (int nt2 = 0; nt2 < 8; nt2++) {
                uint32_t t[4];
                LDSM4(t, KT + (uint32_t)(nt2 * 16 * FQP + ks * 32) + lq);
                uint32_t b0[2] = {t[0], t[2]}, b1[2] = {t[1], t[3]};
                MMATF32(acc1[2*nt2],   ah, b0);
                MMATF32(acc1[2*nt2+1], ah, b1);
            }
        }

        // ---- exp (no max subtraction) + column sum over n=128
#pragma unroll
        for (int nt = 0; nt < 16; nt++) {
            acc1[nt][0] = __expf(acc1[nt][0]);
            acc1[nt][1] = __expf(acc1[nt][1]);
            acc1[nt][2] = __expf(acc1[nt][2]);
            acc1[nt][3] = __expf(acc1[nt][3]);
            float s0 = acc1[nt][0] + acc1[nt][2];
            float s1 = acc1[nt][1] + acc1[nt][3];
            s0 += __shfl_xor_sync(0xffffffffu, s0, 4);
            s0 += __shfl_xor_sync(0xffffffffu, s0, 8);
            s0 += __shfl_xor_sync(0xffffffffu, s0, 16);
            s1 += __shfl_xor_sync(0xffffffffu, s1, 4);
            s1 += __shfl_xor_sync(0xffffffffu, s1, 8);
            s1 += __shfl_xor_sync(0xffffffffu, s1, 16);
            if (lane < 4) {
                cst[wid * 128 + nt * 8 + lane * 2]     = s0;
                cst[wid * 128 + nt * 8 + lane * 2 + 1] = s1;
            }
        }
        __syncthreads();
        if (tid < 128) {
            float s = 0.f;
#pragma unroll
            for (int w = 0; w < 8; w++) s += cst[w * 128 + tid];
            cst[1024 + tid] = 1.f / s;
        }
        __syncthreads();
#pragma unroll
        for (int nt = 0; nt < 16; nt++) {
            float2 iv = *reinterpret_cast<const float2*>(
                &cst[1024 + nt * 8 + (lane & 3) * 2]);
            acc1[nt][0] *= iv.x; acc1[nt][1] *= iv.y;
            acc1[nt][2] *= iv.x; acc1[nt][3] *= iv.y;
        }

        // ---- MMA2: acc2 += P @ [V | ones]  (bf16x3, full precision)
#pragma unroll
        for (int ks2 = 0; ks2 < 8; ks2++) {
            const float* p0 = acc1[2*ks2];
            const float* p1 = acc1[2*ks2+1];
            uint32_t pah[4], pal[4];
            pah[0] = pk2(p0[0], p0[1]); pal[0] = pk2lo(p0[0], p0[1], pah[0]);
            pah[1] = pk2(p0[2], p0[3]); pal[1] = pk2lo(p0[2], p0[3], pah[1]);
            pah[2] = pk2(p1[0], p1[1]); pal[2] = pk2lo(p1[0], p1[1], pah[2]);
            pah[3] = pk2(p1[2], p1[3]); pal[3] = pk2lo(p1[2], p1[3], pah[3]);
#pragma unroll
            for (int nt2 = 0; nt2 < 5; nt2++) {
                uint32_t th[4], tl[4];
                LDSM4T(th, VHI + (uint32_t)(ks2 * 16 * FPV + nt2 * 32) + lv);
                LDSM4T(tl, VLO + (uint32_t)(ks2 * 16 * FPV + nt2 * 32) + lv);
                uint32_t b0h[2] = {th[0], th[1]}, b0l[2] = {tl[0], tl[1]};
                MMA16816(acc2[2*nt2], pah, b0h);
                MMA16816(acc2[2*nt2], pah, b0l);
                MMA16816(acc2[2*nt2], pal, b0h);
                if (nt2 < 4) {
                    uint32_t b1h[2] = {th[2], th[3]}, b1l[2] = {tl[2], tl[3]};
                    MMA16816(acc2[2*nt2+1], pah, b1h);
                    MMA16816(acc2[2*nt2+1], pah, b1l);
                    MMA16816(acc2[2*nt2+1], pal, b1h);
                }
            }
        }

        if (c + 1 < 32) CP_WAIT0();
        __syncthreads();
        if (c + 1 < 32) {
            cvt_chunk((c + 1) & 1);
            __syncthreads();
        }
    }

    // ---- epilogue: divide by rowsum (ones column), store O
    float rs0 = __shfl_sync(0xffffffffu, acc2[8][0], lane & ~3);
    float rs2 = __shfl_sync(0xffffffffu, acc2[8][2], lane & ~3);
    float i0 = 1.f / rs0, i2 = 1.f / rs2;
    int r0 = mrow + (lane >> 2);
    float* Ob = O + (long)b * NN * DD + h * DH;
#pragma unroll
    for (int nt = 0; nt < 8; nt++) {
        int cc = nt * 8 + (lane & 3) * 2;
        float2 v0, v1;
        v0.x = acc2[nt][0] * i0; v0.y = acc2[nt][1] * i0;
        v1.x = acc2[nt][2] * i2; v1.y = acc2[nt][3] * i2;
        *reinterpret_cast<float2*>(&Ob[(long)r0 * DD + cc]) = v0;
        *reinterpret_cast<float2*>(&Ob[(long)(r0 + 8) * DD + cc]) = v1;
    }
}

// ---------------- launch ----------------------------------------------------
extern "C" void kernel_launch(void* const* d_in, const int* in_sizes, int n_in,
                              void* d_out, int out_size)
{
    const float* q  = (const float*)d_in[0];
    const float* k  = (const float*)d_in[1];
    const float* v  = (const float*)d_in[2];
    const float* Wq = (const float*)d_in[3];
    const float* Wk = (const float*)d_in[4];
    const float* Wv = (const float*)d_in[5];
    const float* Wo = (const float*)d_in[6];
    float* out = (float*)d_out;

    float *Qp, *Kp, *Vp, *O;
    cudaGetSymbolAddress((void**)&Qp, g_Qp);
    cudaGetSymbolAddress((void**)&Kp, g_Kp);
    cudaGetSymbolAddress((void**)&Vp, g_Vp);
    cudaGetSymbolAddress((void**)&O,  g_O);

    const int SZG = 2 * (128 * 144 + 64 * 144);   // 55296
    cudaFuncSetAttribute((const void*)gemm_tf32,
                         cudaFuncAttributeMaxDynamicSharedMemorySize, SZG);
    cudaFuncSetAttribute((const void*)fused_attn,
                         cudaFuncAttributeMaxDynamicSharedMemorySize, FUSED_SMEM);

    // all projections: 1-pass tf32 (rel ~2e-4 each; S-path attenuated by softmax)
    gemm_tf32<<<dim3(DD/64, (BB*NN)/128), 256, SZG>>>(
        q, Wq, Qp, DD, DD, DD, DD, 1.f);
    gemm_tf32<<<dim3(DD/64, (BB*LL)/128), 256, SZG>>>(
        k, Wk, Kp, DD, DD, DD, DD, 1.f);
    gemm_tf32<<<dim3(DD/64, (BB*LL)/128), 256, SZG>>>(
        v, Wv, Vp, DD, DD, DD, DD, 1.f);

    // fused: scores (tf32) + inverted softmax + L1 renorm + AV (bf16x3)
    fused_attn<<<BH, 256, FUSED_SMEM>>>(Qp, Kp, Vp, O);

    // output projection: 1-pass tf32
    gemm_tf32<<<dim3(DD/64, (BB*NN)/128), 256, SZG>>>(
        O, Wo, out, DD, DD, DD, DD, 1.f);
}

// round 14
// speedup vs baseline: 1.1285x; 1.1098x over previous
#include <cuda_runtime.h>
#include <cuda_bf16.h>
#include <cstdint>

// Problem constants
#define BB 8
#define NN 128
#define LL 4096
#define DD 1024
#define HH 16
#define DH 64
#define BH (BB*HH)          // 128

// ---------------- scratch (device globals) ----------------
__device__ float g_Qp[BB*NN*DD];            // 4 MB
__device__ float g_Kp[BB*LL*DD];            // 128 MB
__device__ float g_Vp[BB*LL*DD];            // 128 MB
__device__ float g_O [BB*NN*DD];            // 4 MB

// ---------------- helpers ----------------
__device__ __forceinline__ uint32_t smem_u32(const void* p) {
    uint32_t a;
    asm("{ .reg .u64 t; cvta.to.shared.u64 t, %1; cvt.u32.u64 %0, t; }"
        : "=r"(a) : "l"(p));
    return a;
}
__device__ __forceinline__ uint32_t pk2(float x, float y) {
    uint32_t r;
    asm("cvt.rn.bf16x2.f32 %0, %1, %2;" : "=r"(r) : "f"(y), "f"(x));
    return r;
}
__device__ __forceinline__ uint32_t pk2lo(float x, float y, uint32_t h) {
    float hx = __uint_as_float(h << 16);
    float hy = __uint_as_float(h & 0xFFFF0000u);
    uint32_t r;
    asm("cvt.rn.bf16x2.f32 %0, %1, %2;" : "=r"(r) : "f"(y - hy), "f"(x - hx));
    return r;
}
__device__ __forceinline__ void pack_hl(float4 v, uint64_t& H, uint64_t& L) {
    uint32_t h01 = pk2(v.x, v.y);
    uint32_t h23 = pk2(v.z, v.w);
    uint32_t l01 = pk2lo(v.x, v.y, h01);
    uint32_t l23 = pk2lo(v.z, v.w, h23);
    H = (uint64_t)h01 | ((uint64_t)h23 << 32);
    L = (uint64_t)l01 | ((uint64_t)l23 << 32);
}
__device__ __forceinline__ uint64_t pack_h(float4 v) {
    uint32_t h01 = pk2(v.x, v.y);
    uint32_t h23 = pk2(v.z, v.w);
    return (uint64_t)h01 | ((uint64_t)h23 << 32);
}
__device__ __forceinline__ uint32_t f2tf(float x) {
    uint32_t r;
    asm("cvt.rna.tf32.f32 %0, %1;" : "=r"(r) : "f"(x));
    return r;
}
__device__ __forceinline__ void sts64(uint32_t addr, uint64_t v) {
    asm volatile("st.shared.b64 [%0], %1;" :: "r"(addr), "l"(v) : "memory");
}
__device__ __forceinline__ void sts32(uint32_t addr, uint32_t v) {
    asm volatile("st.shared.b32 [%0], %1;" :: "r"(addr), "r"(v) : "memory");
}
__device__ __forceinline__ void sts_tf4(uint32_t addr, float4 v) {
    asm volatile("st.shared.v4.b32 [%0], {%1,%2,%3,%4};"
        :: "r"(addr), "r"(f2tf(v.x)), "r"(f2tf(v.y)),
           "r"(f2tf(v.z)), "r"(f2tf(v.w)) : "memory");
}
__device__ __forceinline__ float4 lds128f(uint32_t addr) {
    float4 v;
    asm volatile("ld.shared.v4.f32 {%0,%1,%2,%3}, [%4];"
        : "=f"(v.x), "=f"(v.y), "=f"(v.z), "=f"(v.w) : "r"(addr));
    return v;
}
__device__ __forceinline__ void cp16(uint32_t s, const void* g) {
    asm volatile("cp.async.cg.shared.global [%0], [%1], 16;" :: "r"(s), "l"(g));
}
#define CP_COMMIT() asm volatile("cp.async.commit_group;" ::: "memory")
#define CP_WAIT0()  asm volatile("cp.async.wait_group 0;" ::: "memory")

#define LDSM4(r, a) \
    asm volatile("ldmatrix.sync.aligned.m8n8.x4.shared.b16 {%0,%1,%2,%3}, [%4];" \
        : "=r"((r)[0]), "=r"((r)[1]), "=r"((r)[2]), "=r"((r)[3]) : "r"(a))
#define LDSM4T(r, a) \
    asm volatile("ldmatrix.sync.aligned.m8n8.x4.trans.shared.b16 {%0,%1,%2,%3}, [%4];" \
        : "=r"((r)[0]), "=r"((r)[1]), "=r"((r)[2]), "=r"((r)[3]) : "r"(a))

#define MMA16816(d, a, b) \
    asm volatile("mma.sync.aligned.m16n8k16.row.col.f32.bf16.bf16.f32 " \
        "{%0,%1,%2,%3}, {%4,%5,%6,%7}, {%8,%9}, {%0,%1,%2,%3};" \
        : "+f"((d)[0]), "+f"((d)[1]), "+f"((d)[2]), "+f"((d)[3]) \
        : "r"((a)[0]), "r"((a)[1]), "r"((a)[2]), "r"((a)[3]), \
          "r"((b)[0]), "r"((b)[1]))

#define MMATF32(d, a, b) \
    asm volatile("mma.sync.aligned.m16n8k8.row.col.f32.tf32.tf32.f32 " \
        "{%0,%1,%2,%3}, {%4,%5,%6,%7}, {%8,%9}, {%0,%1,%2,%3};" \
        : "+f"((d)[0]), "+f"((d)[1]), "+f"((d)[2]), "+f"((d)[3]) \
        : "r"((a)[0]), "r"((a)[1]), "r"((a)[2]), "r"((a)[3]), \
          "r"((b)[0]), "r"((b)[1]))

// ---------------- bf16 1-pass NT GEMM (K projection) -------------------------
// Tile 128x64, BK = 32 fp32, 8 warps = 4(m) x 2(n), occ 2. 144B pitch rows.
__global__ void __launch_bounds__(256, 2)
gemm_bf16(const float* __restrict__ A, const float* __restrict__ Bp,
          float* __restrict__ Cg, int K, int lda, int ldb, int ldc, float alpha)
{
    constexpr int ABYTES = 128 * 144;
    constexpr int BBYTES = 64 * 144;
    constexpr int STAGE  = ABYTES + BBYTES;

    extern __shared__ char smem[];
    const uint32_t sb = smem_u32(smem);

    const int tid  = threadIdx.x;
    const int wid  = tid >> 5, lane = tid & 31;
    const int wm   = wid & 3, wn = wid >> 2;

    const int m0 = blockIdx.y * 128;
    const int n0 = blockIdx.x * 64;

    float acc[2][4][4];
#pragma unroll
    for (int i = 0; i < 2; i++)
#pragma unroll
        for (int j = 0; j < 4; j++)
#pragma unroll
            for (int q = 0; q < 4; q++) acc[i][j][q] = 0.f;

    const int NC = K >> 5;
    float4 ra[4], rb[2];
    const int lrow = tid >> 3;
    const int lseg = tid & 7;

    auto ldg = [&](int c) {
        const int k0 = c << 5;
#pragma unroll
        for (int i = 0; i < 4; i++)
            ra[i] = *reinterpret_cast<const float4*>(
                &A[(long)(m0 + lrow + (i << 5)) * lda + k0 + (lseg << 2)]);
#pragma unroll
        for (int i = 0; i < 2; i++)
            rb[i] = *reinterpret_cast<const float4*>(
                &Bp[(long)(n0 + lrow + (i << 5)) * ldb + k0 + (lseg << 2)]);
    };
    auto sts_stage = [&](int st) {
        const uint32_t abase = sb + st * STAGE;
        const uint32_t bbase = abase + ABYTES;
#pragma unroll
        for (int i = 0; i < 4; i++)
            sts64(abase + (uint32_t)((lrow + (i << 5)) * 144 + (lseg << 3)),
                  pack_h(ra[i]));
#pragma unroll
        for (int i = 0; i < 2; i++)
            sts64(bbase + (uint32_t)((lrow + (i << 5)) * 144 + (lseg << 3)),
                  pack_h(rb[i]));
    };
    auto compute = [&](int st) {
        const uint32_t abase = sb + st * STAGE;
        const uint32_t bbase = abase + ABYTES;
        const uint32_t lmo = (uint32_t)(((lane & 15) * 144) + ((lane >> 4) << 4));
#pragma unroll
        for (int ks = 0; ks < 2; ks++) {
            uint32_t ah[2][4];
#pragma unroll
            for (int mt = 0; mt < 2; mt++)
                LDSM4(ah[mt], abase + (uint32_t)((wm * 32 + mt * 16) * 144 + ks * 32) + lmo);
            uint32_t bhp[4][2];
#pragma unroll
            for (int j = 0; j < 2; j++) {
                uint32_t t[4];
                LDSM4(t, bbase + (uint32_t)((wn * 32 + j * 16) * 144 + ks * 32) + lmo);
                bhp[2*j][0] = t[0]; bhp[2*j][1] = t[2];
                bhp[2*j+1][0] = t[1]; bhp[2*j+1][1] = t[3];
            }
#pragma unroll
            for (int mt = 0; mt < 2; mt++)
#pragma unroll
                for (int nt = 0; nt < 4; nt++)
                    MMA16816(acc[mt][nt], ah[mt], bhp[nt]);
        }
    };

    ldg(0);
    sts_stage(0);
    __syncthreads();

    for (int c = 0; c < NC; c++) {
        if (c + 1 < NC) ldg(c + 1);
        compute(c & 1);
        if (c + 1 < NC) sts_stage((c + 1) & 1);
        __syncthreads();
    }

#pragma unroll
    for (int mt = 0; mt < 2; mt++) {
        int mr = m0 + wm * 32 + mt * 16 + (lane >> 2);
#pragma unroll
        for (int nt = 0; nt < 4; nt++) {
            int col = n0 + wn * 32 + nt * 8 + (lane & 3) * 2;
            float2 v0, v1;
            v0.x = acc[mt][nt][0] * alpha; v0.y = acc[mt][nt][1] * alpha;
            v1.x = acc[mt][nt][2] * alpha; v1.y = acc[mt][nt][3] * alpha;
            *reinterpret_cast<float2*>(&Cg[(long)mr * ldc + col]) = v0;
            *reinterpret_cast<float2*>(&Cg[(long)(mr + 8) * ldc + col]) = v1;
        }
    }
}

// ---------------- tf32 NT GEMM (Q, V, O projections) -------------------------
// Tile 128x64, BK = 32 fp32 (= 4 k8 steps), occ 2. 144B pitch rows.
__global__ void __launch_bounds__(256, 2)
gemm_tf32(const float* __restrict__ A, const float* __restrict__ Bp,
          float* __restrict__ Cg, int K, int lda, int ldb, int ldc, float alpha)
{
    constexpr int ABYTES = 128 * 144;
    constexpr int BBYTES = 64 * 144;
    constexpr int STAGE  = ABYTES + BBYTES;

    extern __shared__ char smem[];
    const uint32_t sb = smem_u32(smem);

    const int tid  = threadIdx.x;
    const int wid  = tid >> 5, lane = tid & 31;
    const int wm   = wid & 3, wn = wid >> 2;

    const int m0 = blockIdx.y * 128;
    const int n0 = blockIdx.x * 64;

    float acc[2][4][4];
#pragma unroll
    for (int i = 0; i < 2; i++)
#pragma unroll
        for (int j = 0; j < 4; j++)
#pragma unroll
            for (int q = 0; q < 4; q++) acc[i][j][q] = 0.f;

    const int NC = K >> 5;
    float4 ra[4], rb[2];
    const int lrow = tid >> 3;
    const int lseg = tid & 7;

    auto ldg = [&](int c) {
        const int k0 = c << 5;
#pragma unroll
        for (int i = 0; i < 4; i++)
            ra[i] = *reinterpret_cast<const float4*>(
                &A[(long)(m0 + lrow + (i << 5)) * lda + k0 + (lseg << 2)]);
#pragma unroll
        for (int i = 0; i < 2; i++)
            rb[i] = *reinterpret_cast<const float4*>(
                &Bp[(long)(n0 + lrow + (i << 5)) * ldb + k0 + (lseg << 2)]);
    };
    auto sts_stage = [&](int st) {
        const uint32_t abase = sb + st * STAGE;
        const uint32_t bbase = abase + ABYTES;
#pragma unroll
        for (int i = 0; i < 4; i++)
            sts_tf4(abase + (uint32_t)((lrow + (i << 5)) * 144 + (lseg << 4)), ra[i]);
#pragma unroll
        for (int i = 0; i < 2; i++)
            sts_tf4(bbase + (uint32_t)((lrow + (i << 5)) * 144 + (lseg << 4)), rb[i]);
    };
    auto compute = [&](int st) {
        const uint32_t abase = sb + st * STAGE;
        const uint32_t bbase = abase + ABYTES;
        const uint32_t lmo = (uint32_t)(((lane & 15) * 144) + ((lane >> 4) << 4));
#pragma unroll
        for (int ks = 0; ks < 4; ks++) {
            uint32_t ah[2][4];
#pragma unroll
            for (int mt = 0; mt < 2; mt++)
                LDSM4(ah[mt], abase + (uint32_t)((wm * 32 + mt * 16) * 144 + ks * 32) + lmo);
            uint32_t bp[4][2];
#pragma unroll
            for (int j = 0; j < 2; j++) {
                uint32_t t[4];
                LDSM4(t, bbase + (uint32_t)((wn * 32 + j * 16) * 144 + ks * 32) + lmo);
                bp[2*j][0] = t[0]; bp[2*j][1] = t[2];
                bp[2*j+1][0] = t[1]; bp[2*j+1][1] = t[3];
            }
#pragma unroll
            for (int mt = 0; mt < 2; mt++)
#pragma unroll
                for (int nt = 0; nt < 4; nt++)
                    MMATF32(acc[mt][nt], ah[mt], bp[nt]);
        }
    };

    ldg(0);
    sts_stage(0);
    __syncthreads();

    for (int c = 0; c < NC; c++) {
        if (c + 1 < NC) ldg(c + 1);
        compute(c & 1);
        if (c + 1 < NC) sts_stage((c + 1) & 1);
        __syncthreads();
    }

#pragma unroll
    for (int mt = 0; mt < 2; mt++) {
        int mr = m0 + wm * 32 + mt * 16 + (lane >> 2);
#pragma unroll
        for (int nt = 0; nt < 4; nt++) {
            int col = n0 + wn * 32 + nt * 8 + (lane & 3) * 2;
            float2 v0, v1;
            v0.x = acc[mt][nt][0] * alpha; v0.y = acc[mt][nt][1] * alpha;
            v1.x = acc[mt][nt][2] * alpha; v1.y = acc[mt][nt][3] * alpha;
            *reinterpret_cast<float2*>(&Cg[(long)mr * ldc + col]) = v0;
            *reinterpret_cast<float2*>(&Cg[(long)(mr + 8) * ldc + col]) = v1;
        }
    }
}

// ---------------- fused attention (R13 proven: tf32 MMA1 + bf16x3 MMA2) ------
#define FQP 272            // Q/K tf32 pitch (256B data + 16 pad)
#define FPV 176            // V bf16 plane pitch
#define QT_O 0             // 128*272 = 34816
#define KT_O 34816         // 2 stages x 34816 = 69632
#define VHI_O 104448       // 22528
#define VLO_O 126976       // 22528
#define STV_O 149504       // 32768 (V fp32 staging)
#define CST_O 182272       // 4608
#define FUSED_SMEM 186880

__global__ void __launch_bounds__(256, 1)
fused_attn(const float* __restrict__ Qp, const float* __restrict__ Kp,
           const float* __restrict__ Vp, float* __restrict__ O)
{
    extern __shared__ char smem[];
    const uint32_t sb = smem_u32(smem);
    float* cst = reinterpret_cast<float*>(smem + CST_O);

    const int tid = threadIdx.x, wid = tid >> 5, lane = tid & 31;
    const int bh = blockIdx.x, b = bh >> 4, h = bh & 15;
    const float* Qg = Qp + (long)b * NN * DD + h * DH;
    const float* Kg = Kp + (long)b * LL * DD + h * DH;
    const float* Vg = Vp + (long)b * LL * DD + h * DH;

    const uint32_t QT  = sb + QT_O;
    const uint32_t VHI = sb + VHI_O, VLO = sb + VLO_O;
    const uint32_t STV = sb + STV_O;

    for (int r = tid; r < 128; r += 256) {
        uint32_t ro = (uint32_t)r * FPV;
#pragma unroll
        for (int cb = 0; cb < 4; cb++) {
            sts32(VHI + ro + 128 + cb * 4, 0x3F803F80u);
            sts32(VLO + ro + 128 + cb * 4, 0u);
            sts32(VHI + ro + 144 + cb * 4, 0u);
            sts32(VLO + ro + 144 + cb * 4, 0u);
        }
    }

    const float SCALE = 0.03125f;
#pragma unroll
    for (int i = 0; i < 8; i++) {
        int idx = tid + i * 256;
        int r = idx >> 4, s = idx & 15;
        float4 v = *reinterpret_cast<const float4*>(&Qg[(long)r * DD + s * 4]);
        v.x *= SCALE; v.y *= SCALE; v.z *= SCALE; v.w *= SCALE;
        sts_tf4(QT + (uint32_t)(r * FQP + s * 16), v);
    }

    auto prefetch = [&](int c, int st) {
        long l0 = (long)c * 128;
        const uint32_t kt = sb + KT_O + (uint32_t)st * 34816u;
#pragma unroll
        for (int i = 0; i < 8; i++) {
            int idx = tid + i * 256;
            int r = idx >> 4, s = idx & 15;
            cp16(kt + (uint32_t)(r * FQP + s * 16), &Kg[(l0 + r) * DD + s * 4]);
            cp16(STV + (uint32_t)(r * 256 + s * 16), &Vg[(l0 + r) * DD + s * 4]);
        }
        CP_COMMIT();
    };
    auto cvt_chunk = [&](int st) {
        const uint32_t kt = sb + KT_O + (uint32_t)st * 34816u;
        const float4* stv = reinterpret_cast<const float4*>(smem + STV_O);
#pragma unroll
        for (int i = 0; i < 8; i++) {
            int idx = tid + i * 256;
            int r = idx >> 4, s = idx & 15;
            uint32_t a = kt + (uint32_t)(r * FQP + s * 16);
            sts_tf4(a, lds128f(a));                    // K: fp32 -> tf32 in place
            uint64_t H, L;
            pack_hl(stv[r * 16 + s], H, L);            // V: staging -> bf16 planes
            sts64(VHI + r * FPV + s * 8, H);
            sts64(VLO + r * FPV + s * 8, L);
        }
    };

    float acc2[9][4];
#pragma unroll
    for (int i = 0; i < 9; i++)
#pragma unroll
        for (int j = 0; j < 4; j++) acc2[i][j] = 0.f;

    const int mrow = wid * 16;
    const uint32_t lq = (uint32_t)((lane & 15) * FQP + ((lane >> 4) << 4));
    const uint32_t lv = (uint32_t)((lane & 15) * FPV + ((lane >> 4) << 4));

    prefetch(0, 0);
    CP_WAIT0();
    __syncthreads();
    cvt_chunk(0);
    __syncthreads();

    for (int c = 0; c < 32; c++) {
        if (c + 1 < 32) prefetch(c + 1, (c + 1) & 1);

        const uint32_t KT = sb + KT_O + (uint32_t)(c & 1) * 34816u;

        float acc1[16][4];
#pragma unroll
        for (int i = 0; i < 16; i++)
#pragma unroll
            for (int j = 0; j < 4; j++) acc1[i][j] = 0.f;

#pragma unroll
        for (int ks = 0; ks < 8; ks++) {
            uint32_t ah[4];
            LDSM4(ah, QT + (uint32_t)(mrow * FQP + ks * 32) + lq);
#pragma unroll
            for (int nt2 = 0; nt2 < 8; nt2++) {
                uint32_t t[4];
                LDSM4(t, KT + (uint32_t)(nt2 * 16 * FQP + ks * 32) + lq);
                uint32_t b0[2] = {t[0], t[2]}, b1[2] = {t[1], t[3]};
                MMATF32(acc1[2*nt2],   ah, b0);
                MMATF32(acc1[2*nt2+1], ah, b1);
            }
        }

#pragma unroll
        for (int nt = 0; nt < 16; nt++) {
            acc1[nt][0] = __expf(acc1[nt][0]);
            acc1[nt][1] = __expf(acc1[nt][1]);
            acc1[nt][2] = __expf(acc1[nt][2]);
            acc1[nt][3] = __expf(acc1[nt][3]);
            float s0 = acc1[nt][0] + acc1[nt][2];
            float s1 = acc1[nt][1] + acc1[nt][3];
            s0 += __shfl_xor_sync(0xffffffffu, s0, 4);
            s0 += __shfl_xor_sync(0xffffffffu, s0, 8);
            s0 += __shfl_xor_sync(0xffffffffu, s0, 16);
            s1 += __shfl_xor_sync(0xffffffffu, s1, 4);
            s1 += __shfl_xor_sync(0xffffffffu, s1, 8);
            s1 += __shfl_xor_sync(0xffffffffu, s1, 16);
            if (lane < 4) {
                cst[wid * 128 + nt * 8 + lane * 2]     = s0;
                cst[wid * 128 + nt * 8 + lane * 2 + 1] = s1;
            }
        }
        __syncthreads();
        if (tid < 128) {
            float s = 0.f;
#pragma unroll
            for (int w = 0; w < 8; w++) s += cst[w * 128 + tid];
            cst[1024 + tid] = 1.f / s;
        }
        __syncthreads();
#pragma unroll
        for (int nt = 0; nt < 16; nt++) {
            float2 iv = *reinterpret_cast<const float2*>(
                &cst[1024 + nt * 8 + (lane & 3) * 2]);
            acc1[nt][0] *= iv.x; acc1[nt][1] *= iv.y;
            acc1[nt][2] *= iv.x; acc1[nt][3] *= iv.y;
        }

#pragma unroll
        for (int ks2 = 0; ks2 < 8; ks2++) {
            const float* p0 = acc1[2*ks2];
            const float* p1 = acc1[2*ks2+1];
            uint32_t pah[4], pal[4];
            pah[0] = pk2(p0[0], p0[1]); pal[0] = pk2lo(p0[0], p0[1], pah[0]);
            pah[1] = pk2(p0[2], p0[3]); pal[1] = pk2lo(p0[2], p0[3], pah[1]);
            pah[2] = pk2(p1[0], p1[1]); pal[2] = pk2lo(p1[0], p1[1], pah[2]);
            pah[3] = pk2(p1[2], p1[3]); pal[3] = pk2lo(p1[2], p1[3], pah[3]);
#pragma unroll
            for (int nt2 = 0; nt2 < 5; nt2++) {
                uint32_t th[4], tl[4];
                LDSM4T(th, VHI + (uint32_t)(ks2 * 16 * FPV + nt2 * 32) + lv);
                LDSM4T(tl, VLO + (uint32_t)(ks2 * 16 * FPV + nt2 * 32) + lv);
                uint32_t b0h[2] = {th[0], th[1]}, b0l[2] = {tl[0], tl[1]};
                MMA16816(acc2[2*nt2], pah, b0h);
                MMA16816(acc2[2*nt2], pah, b0l);
                MMA16816(acc2[2*nt2], pal, b0h);
                if (nt2 < 4) {
                    uint32_t b1h[2] = {th[2], th[3]}, b1l[2] = {tl[2], tl[3]};
                    MMA16816(acc2[2*nt2+1], pah, b1h);
                    MMA16816(acc2[2*nt2+1], pah, b1l);
                    MMA16816(acc2[2*nt2+1], pal, b1h);
                }
            }
        }

        if (c + 1 < 32) CP_WAIT0();
        __syncthreads();
        if (c + 1 < 32) {
            cvt_chunk((c + 1) & 1);
            __syncthreads();
        }
    }

    float rs0 = __shfl_sync(0xffffffffu, acc2[8][0], lane & ~3);
    float rs2 = __shfl_sync(0xffffffffu, acc2[8][2], lane & ~3);
    float i0 = 1.f / rs0, i2 = 1.f / rs2;
    int r0 = mrow + (lane >> 2);
    float* Ob = O + (long)b * NN * DD + h * DH;
#pragma unroll
    for (int nt = 0; nt < 8; nt++) {
        int cc = nt * 8 + (lane & 3) * 2;
        float2 v0, v1;
        v0.x = acc2[nt][0] * i0; v0.y = acc2[nt][1] * i0;
        v1.x = acc2[nt][2] * i2; v1.y = acc2[nt][3] * i2;
        *reinterpret_cast<float2*>(&Ob[(long)r0 * DD + cc]) = v0;
        *reinterpret_cast<float2*>(&Ob[(long)(r0 + 8) * DD + cc]) = v1;
    }
}

// ---------------- launch ----------------------------------------------------
extern "C" void kernel_launch(void* const* d_in, const int* in_sizes, int n_in,
                              void* d_out, int out_size)
{
    const float* q  = (const float*)d_in[0];
    const float* k  = (const float*)d_in[1];
    const float* v  = (const float*)d_in[2];
    const float* Wq = (const float*)d_in[3];
    const float* Wk = (const float*)d_in[4];
    const float* Wv = (const float*)d_in[5];
    const float* Wo = (const float*)d_in[6];
    float* out = (float*)d_out;

    float *Qp, *Kp, *Vp, *O;
    cudaGetSymbolAddress((void**)&Qp, g_Qp);
    cudaGetSymbolAddress((void**)&Kp, g_Kp);
    cudaGetSymbolAddress((void**)&Vp, g_Vp);
    cudaGetSymbolAddress((void**)&O,  g_O);

    const int SZG = 2 * (128 * 144 + 64 * 144);   // 55296
    cudaFuncSetAttribute((const void*)gemm_bf16,
                         cudaFuncAttributeMaxDynamicSharedMemorySize, SZG);
    cudaFuncSetAttribute((const void*)gemm_tf32,
                         cudaFuncAttributeMaxDynamicSharedMemorySize, SZG);
    cudaFuncSetAttribute((const void*)fused_attn,
                         cudaFuncAttributeMaxDynamicSharedMemorySize, FUSED_SMEM);

    // Q projection: tf32 (cheap, accurate enough; S-path attenuated)
    gemm_tf32<<<dim3(DD/64, (BB*NN)/128), 256, SZG>>>(
        q, Wq, Qp, DD, DD, DD, DD, 1.f);
    // K projection: bf16 1-pass — fastest; error enters only via softmax weights
    gemm_bf16<<<dim3(DD/64, (BB*LL)/128), 256, SZG>>>(
        k, Wk, Kp, DD, DD, DD, DD, 1.f);
    // V projection: tf32 — V-path errors hit output directly, tf32 is enough
    gemm_tf32<<<dim3(DD/64, (BB*LL)/128), 256, SZG>>>(
        v, Wv, Vp, DD, DD, DD, DD, 1.f);

    // fused: scores (tf32) + inverted softmax + L1 renorm + AV (bf16x3)
    fused_attn<<<BH, 256, FUSED_SMEM>>>(Qp, Kp, Vp, O);

    // output projection: tf32
    gemm_tf32<<<dim3(DD/64, (BB*NN)/128), 256, SZG>>>(
        O, Wo, out, DD, DD, DD, DD, 1.f);
}